// round 13
// baseline (speedup 1.0000x reference)
#include <cuda_runtime.h>
#include <cstdint>

#define EMB 128
#define NMAX 50000
#define EMAX 800000
#define FULLM 0xffffffffu

typedef unsigned long long ull;

// ---------------- f32x2 packed helpers --------------------------------------------
#define FMA2(d, a, b, c) \
    asm("fma.rn.f32x2 %0, %1, %2, %3;" : "=l"(d) : "l"(a), "l"(b), "l"(c))
#define PACK2(d, x) \
    asm("mov.b64 %0, {%1, %1};" : "=l"(d) : "f"(x))
#define PACKAB(d, x, y) \
    asm("mov.b64 %0, {%1, %2};" : "=l"(d) : "f"(x), "f"(y))
#define UNPACK2(lo, hi, v) \
    asm("mov.b64 {%0, %1}, %2;" : "=f"(lo), "=f"(hi) : "l"(v))

// ---------------- scratch (static device globals; no allocation) ----------------
__device__ float g_aggr[NMAX * EMB];          // 25.6 MB
__device__ float g_h1[NMAX * 2 * EMB];        // 51.2 MB
__device__ float g_stat[768];                 // sum1[256] sq1[256] sum2[128] sq2[128]
__device__ int   g_is64;
__device__ int   g_deg[NMAX];
__device__ int   g_off[NMAX + 1];
__device__ int   g_cur[NMAX];
__device__ int   g_bsum[64];
__device__ int   g_boff[64];
__device__ uint2 g_elist[EMAX];               // (src, edge_id) sorted by dst

// ---------------- zero counters + stats + detect dtype (merged) -------------------
__global__ void zero_kernel(const unsigned long long* __restrict__ p, int n) {
    int i = blockIdx.x * blockDim.x + threadIdx.x;
    if (i < n) g_deg[i] = 0;
    if (blockIdx.x == 0) {
        for (int j = threadIdx.x; j < 768; j += blockDim.x) g_stat[j] = 0.0f;
        if (threadIdx.x == 0) {
            int ok = 1;
            for (int k = 0; k < 64; k++)
                if (p[k] >= (unsigned long long)n) { ok = 0; break; }
            g_is64 = ok;
        }
    }
}

__device__ __forceinline__ void load_edge(const void* eiv, int e, int E,
                                          int& src, int& dst) {
    if (g_is64) {
        const long long* pe = (const long long*)eiv;
        src = (int)pe[e]; dst = (int)pe[(size_t)E + e];
    } else {
        const int* pe = (const int*)eiv;
        src = pe[e]; dst = pe[(size_t)E + e];
    }
}

// ---------------- CSR build: histogram -------------------------------------------
__global__ void hist_kernel(const void* __restrict__ eiv, int E) {
    int e = blockIdx.x * blockDim.x + threadIdx.x;
    if (e >= E) return;
    int src, dst; load_edge(eiv, e, E, src, dst);
    atomicAdd(&g_deg[dst], 1);
}

// ---------------- scan phase 1: 256 threads x 4 elems (1024/block) ----------------
__global__ __launch_bounds__(256) void scan1_kernel(int n) {
    __shared__ int wsum[8];
    int tid = threadIdx.x;
    int lane = tid & 31, wid = tid >> 5;
    int i0 = blockIdx.x * 1024 + tid * 4;
    int v0 = (i0 + 0 < n) ? g_deg[i0 + 0] : 0;
    int v1 = (i0 + 1 < n) ? g_deg[i0 + 1] : 0;
    int v2 = (i0 + 2 < n) ? g_deg[i0 + 2] : 0;
    int v3 = (i0 + 3 < n) ? g_deg[i0 + 3] : 0;
    int tsum = v0 + v1 + v2 + v3;
    int x = tsum;
#pragma unroll
    for (int off = 1; off < 32; off <<= 1) {
        int t = __shfl_up_sync(FULLM, x, off);
        if (lane >= off) x += t;
    }
    if (lane == 31) wsum[wid] = x;
    __syncthreads();
    if (wid == 0) {
        int s = (lane < 8) ? wsum[lane] : 0;
#pragma unroll
        for (int off = 1; off < 8; off <<= 1) {
            int t = __shfl_up_sync(FULLM, s, off);
            if (lane >= off) s += t;
        }
        if (lane < 8) wsum[lane] = s;
        if (lane == 7) g_bsum[blockIdx.x] = s;
    }
    __syncthreads();
    int wbase = (wid > 0) ? wsum[wid - 1] : 0;
    int excl = wbase + x - tsum;
    if (i0 + 0 < n) g_off[i0 + 0] = excl;         excl += v0;
    if (i0 + 1 < n) g_off[i0 + 1] = excl;         excl += v1;
    if (i0 + 2 < n) g_off[i0 + 2] = excl;         excl += v2;
    if (i0 + 3 < n) g_off[i0 + 3] = excl;
}

// ---------------- scan phase 2: scan the block sums (1 warp) ----------------------
__global__ void scan2_kernel(int nblocks, int n) {
    int lane = threadIdx.x;
    int v = (lane < nblocks) ? g_bsum[lane] : 0;
    int x = v;
#pragma unroll
    for (int off = 1; off < 32; off <<= 1) {
        int t = __shfl_up_sync(FULLM, x, off);
        if (lane >= off) x += t;
    }
    if (nblocks > 32) {
        __shared__ int c32;
        if (lane == 31) c32 = x;
        __syncwarp();
        int v2 = (lane + 32 < nblocks) ? g_bsum[lane + 32] : 0;
        int x2 = v2;
#pragma unroll
        for (int off = 1; off < 32; off <<= 1) {
            int t = __shfl_up_sync(FULLM, x2, off);
            if (lane >= off) x2 += t;
        }
        if (lane < nblocks) g_boff[lane] = x - v;
        if (lane + 32 < nblocks) g_boff[lane + 32] = c32 + x2 - v2;
        if (lane == 31) g_off[n] = c32 + __shfl_sync(FULLM, x2, 31);
    } else {
        if (lane < nblocks) g_boff[lane] = x - v;
        if (lane == 31) g_off[n] = x;
    }
}

// ---------------- scan phase 3: 256 threads x 4 elems -----------------------------
__global__ __launch_bounds__(256) void scan3_kernel(int n) {
    int i0 = blockIdx.x * 1024 + threadIdx.x * 4;
    int bo = g_boff[blockIdx.x];
#pragma unroll
    for (int q = 0; q < 4; q++) {
        int i = i0 + q;
        if (i < n) {
            int o = g_off[i] + bo;
            g_off[i] = o;
            g_cur[i] = o;
        }
    }
}

// ---------------- CSR build: scatter ----------------------------------------------
__global__ void scatter_kernel(const void* __restrict__ eiv, int E) {
    int e = blockIdx.x * blockDim.x + threadIdx.x;
    if (e >= E) return;
    int src, dst; load_edge(eiv, e, E, src, dst);
    int pos = atomicAdd(&g_cur[dst], 1);
    g_elist[pos] = make_uint2((unsigned)src, (unsigned)e);
}

// ---------------- aggregation: PERSISTENT warps, W in regs, 2-edge FFMA2 ----------
#define AGGR_BLOCKS 444   // up to 3 blocks per SM on 148 SMs

__global__ __launch_bounds__(256) void aggr_kernel(
    const float4* __restrict__ x4, const float* __restrict__ ea,
    const float4* __restrict__ We4, const float4* __restrict__ be4, int n)
{
    __shared__ float2 s_av[8][32][18];
    int t = threadIdx.x, lane = t & 31, warp = t >> 5;

    ull w01[16], w23[16];
#pragma unroll
    for (int k = 0; k < 16; k++) {
        float4 w = We4[k * 32 + lane];
        PACKAB(w01[k], w.x, w.y);
        PACKAB(w23[k], w.z, w.w);
    }
    float4 bia = be4[lane];
    ull b01, b23;
    PACKAB(b01, bia.x, bia.y);
    PACKAB(b23, bia.z, bia.w);

    int stride = gridDim.x * 8;
    for (int dst = blockIdx.x * 8 + warp; dst < n; dst += stride) {
        int beg = g_off[dst], end = g_off[dst + 1];
        float4 acc = make_float4(0.f, 0.f, 0.f, 0.f);

        for (int b = beg; b < end; b += 32) {
            int cnt = min(32, end - b);
            uint2 se = (lane < cnt) ? g_elist[b + lane] : make_uint2(0u, 0u);
            if (lane < cnt) {
                const float4* pa = (const float4*)(ea + (size_t)se.y * 16);
                float4* dstp = (float4*)&s_av[warp][lane][0];
#pragma unroll
                for (int q = 0; q < 4; q++) {
                    float4 a = pa[q];
                    dstp[q * 2 + 0] = make_float4(a.x, a.x, a.y, a.y);
                    dstp[q * 2 + 1] = make_float4(a.z, a.z, a.w, a.w);
                }
            }
            __syncwarp();
            for (int j = 0; j < cnt; j += 2) {
                int j1 = min(j + 1, cnt - 1);
                bool has1 = (j + 1 < cnt);
                int src0 = __shfl_sync(FULLM, (int)se.x, j);
                int src1 = __shfl_sync(FULLM, (int)se.x, j1);
                float4 xv0 = x4[(size_t)src0 * 32 + lane];
                float4 xv1 = x4[(size_t)src1 * 32 + lane];
                ull ma01 = b01, ma23 = b23, mb01 = b01, mb23 = b23;
                const ull* ap0 = (const ull*)&s_av[warp][j][0];
                const ull* ap1 = (const ull*)&s_av[warp][j1][0];
#pragma unroll
                for (int k = 0; k < 16; k++) {
                    ull v0 = ap0[k];
                    ull v1 = ap1[k];
                    FMA2(ma01, v0, w01[k], ma01);
                    FMA2(ma23, v0, w23[k], ma23);
                    FMA2(mb01, v1, w01[k], mb01);
                    FMA2(mb23, v1, w23[k], mb23);
                }
                float f0, f1, f2, f3;
                UNPACK2(f0, f1, ma01);
                UNPACK2(f2, f3, ma23);
                acc.x += fmaxf(f0 + xv0.x, 0.0f);
                acc.y += fmaxf(f1 + xv0.y, 0.0f);
                acc.z += fmaxf(f2 + xv0.z, 0.0f);
                acc.w += fmaxf(f3 + xv0.w, 0.0f);
                if (has1) {
                    UNPACK2(f0, f1, mb01);
                    UNPACK2(f2, f3, mb23);
                    acc.x += fmaxf(f0 + xv1.x, 0.0f);
                    acc.y += fmaxf(f1 + xv1.y, 0.0f);
                    acc.z += fmaxf(f2 + xv1.z, 0.0f);
                    acc.w += fmaxf(f3 + xv1.w, 0.0f);
                }
            }
            __syncwarp();
        }
        *(float4*)(g_aggr + (size_t)dst * EMB + lane * 4) = acc;
    }
}

// ---------------- GEMM1: h1 = ((1+eps)*x + aggr) @ W1 + b1, dbuf + FFMA2 + stats --
#define G1_LOAD(buf, kt) do {                                                       \
    _Pragma("unroll")                                                               \
    for (int l = 0; l < 2; l++) {                                                   \
        int f = t + l * 256;                                                        \
        int r = f >> 2, kq = (f & 3) * 4;                                           \
        int m = row0 + r;                                                           \
        float4 v = make_float4(0.f, 0.f, 0.f, 0.f);                                 \
        if (m < M) {                                                                \
            float4 xv = *(const float4*)(X + (size_t)m * 128 + (kt) + kq);          \
            float4 av = *(const float4*)(g_aggr + (size_t)m * 128 + (kt) + kq);     \
            v.x = fmaf(eps1, xv.x, av.x);                                           \
            v.y = fmaf(eps1, xv.y, av.y);                                           \
            v.z = fmaf(eps1, xv.z, av.z);                                           \
            v.w = fmaf(eps1, xv.w, av.w);                                           \
        }                                                                           \
        As[buf][kq + 0][r] = v.x; As[buf][kq + 1][r] = v.y;                         \
        As[buf][kq + 2][r] = v.z; As[buf][kq + 3][r] = v.w;                         \
    }                                                                               \
    _Pragma("unroll")                                                               \
    for (int l = 0; l < 2; l++) {                                                   \
        int f = t + l * 256;                                                        \
        int kr = f >> 5, nc = (f & 31) * 4;                                         \
        *(float4*)&Bs[buf][kr][nc] =                                                \
            *(const float4*)(W + (size_t)((kt) + kr) * 256 + col0 + nc);            \
    }                                                                               \
} while (0)

#define GEMM_KK(cur) do {                                                           \
    _Pragma("unroll")                                                               \
    for (int kk = 0; kk < 16; kk++) {                                               \
        float a0[8], b0[8];                                                         \
        *(float4*)(a0)     = *(const float4*)&As[cur][kk][ty * 4];                  \
        *(float4*)(a0 + 4) = *(const float4*)&As[cur][kk][64 + ty * 4];             \
        *(float4*)(b0)     = *(const float4*)&Bs[cur][kk][tx * 4];                  \
        *(float4*)(b0 + 4) = *(const float4*)&Bs[cur][kk][64 + tx * 4];             \
        ull bp[4], ap[8];                                                           \
        _Pragma("unroll")                                                           \
        for (int j2 = 0; j2 < 4; j2++) PACKAB(bp[j2], b0[2 * j2], b0[2 * j2 + 1]);  \
        _Pragma("unroll")                                                           \
        for (int i = 0; i < 8; i++) PACK2(ap[i], a0[i]);                            \
        _Pragma("unroll")                                                           \
        for (int i = 0; i < 8; i++)                                                 \
            _Pragma("unroll")                                                       \
            for (int j2 = 0; j2 < 4; j2++)                                          \
                FMA2(acc2[i][j2], ap[i], bp[j2], acc2[i][j2]);                      \
    }                                                                               \
} while (0)

__global__ __launch_bounds__(256, 2) void gemm1_kernel(
    const float* __restrict__ X, const float* __restrict__ W,
    const float* __restrict__ bias, const float* __restrict__ epsp, int M)
{
    __shared__ float As[2][16][132];
    __shared__ float Bs[2][16][132];
    __shared__ float sSum[128], sSq[128];
    const float eps1 = 1.0f + *epsp;
    int t = threadIdx.x;
    int tx = t & 15, ty = t >> 4;
    int row0 = blockIdx.x * 128;
    int col0 = blockIdx.y * 128;
    ull acc2[8][4] = {};

    if (t < 128) { sSum[t] = 0.f; sSq[t] = 0.f; }
    G1_LOAD(0, 0);
    __syncthreads();
    for (int kt = 0; kt < 128; kt += 16) {
        int cur = (kt >> 4) & 1;
        if (kt + 16 < 128) G1_LOAD(cur ^ 1, kt + 16);
        GEMM_KK(cur);
        __syncthreads();
    }
    float acc[8][8];
#pragma unroll
    for (int i = 0; i < 8; i++)
#pragma unroll
        for (int j2 = 0; j2 < 4; j2++)
            UNPACK2(acc[i][2 * j2], acc[i][2 * j2 + 1], acc2[i][j2]);

    float ls[8] = {}, lq[8] = {};
#pragma unroll
    for (int i = 0; i < 8; i++) {
        int m = row0 + ((i < 4) ? (ty * 4 + i) : (64 + ty * 4 + i - 4));
        if (m >= M) continue;
#pragma unroll
        for (int h = 0; h < 2; h++) {
            int c = col0 + h * 64 + tx * 4;
            float4 bb = *(const float4*)(bias + c);
            float4 o;
            o.x = acc[i][h * 4 + 0] + bb.x;
            o.y = acc[i][h * 4 + 1] + bb.y;
            o.z = acc[i][h * 4 + 2] + bb.z;
            o.w = acc[i][h * 4 + 3] + bb.w;
            *(float4*)(g_h1 + (size_t)m * 256 + c) = o;
            ls[h*4+0] += o.x; lq[h*4+0] = fmaf(o.x, o.x, lq[h*4+0]);
            ls[h*4+1] += o.y; lq[h*4+1] = fmaf(o.y, o.y, lq[h*4+1]);
            ls[h*4+2] += o.z; lq[h*4+2] = fmaf(o.z, o.z, lq[h*4+2]);
            ls[h*4+3] += o.w; lq[h*4+3] = fmaf(o.w, o.w, lq[h*4+3]);
        }
    }
#pragma unroll
    for (int h = 0; h < 2; h++)
#pragma unroll
        for (int j = 0; j < 4; j++) {
            int c = h * 64 + tx * 4 + j;
            atomicAdd(&sSum[c], ls[h*4+j]);
            atomicAdd(&sSq[c],  lq[h*4+j]);
        }
    __syncthreads();
    if (t < 128) {
        atomicAdd(&g_stat[col0 + t],       sSum[t]);
        atomicAdd(&g_stat[256 + col0 + t], sSq[t]);
    }
}

// ---------------- GEMM2: BN1 scale/shift computed per block, + fused stats --------
#define G2_LOAD(buf, kt) do {                                                       \
    _Pragma("unroll")                                                               \
    for (int l = 0; l < 2; l++) {                                                   \
        int f = t + l * 256;                                                        \
        int r = f >> 2, kq = (f & 3) * 4;                                           \
        int m = row0 + r;                                                           \
        float4 v = make_float4(0.f, 0.f, 0.f, 0.f);                                 \
        if (m < M) {                                                                \
            float4 hv = *(const float4*)(g_h1 + (size_t)m * 256 + (kt) + kq);       \
            float4 sc = *(const float4*)(sScale1 + (kt) + kq);                      \
            float4 sh = *(const float4*)(sShift1 + (kt) + kq);                      \
            v.x = fmaxf(fmaf(hv.x, sc.x, sh.x), 0.0f);                              \
            v.y = fmaxf(fmaf(hv.y, sc.y, sh.y), 0.0f);                              \
            v.z = fmaxf(fmaf(hv.z, sc.z, sh.z), 0.0f);                              \
            v.w = fmaxf(fmaf(hv.w, sc.w, sh.w), 0.0f);                              \
        }                                                                           \
        As[buf][kq + 0][r] = v.x; As[buf][kq + 1][r] = v.y;                         \
        As[buf][kq + 2][r] = v.z; As[buf][kq + 3][r] = v.w;                         \
    }                                                                               \
    _Pragma("unroll")                                                               \
    for (int l = 0; l < 2; l++) {                                                   \
        int f = t + l * 256;                                                        \
        int kr = f >> 5, nc = (f & 31) * 4;                                         \
        *(float4*)&Bs[buf][kr][nc] =                                                \
            *(const float4*)(W + (size_t)((kt) + kr) * 128 + nc);                   \
    }                                                                               \
} while (0)

__global__ __launch_bounds__(256, 2) void gemm2_kernel(
    const float* __restrict__ W, const float* __restrict__ bias,
    const float* __restrict__ gam, const float* __restrict__ bet,
    float* __restrict__ out, int M, float invM)
{
    __shared__ float As[2][16][132];
    __shared__ float Bs[2][16][132];
    __shared__ float sSum[128], sSq[128];
    __shared__ __align__(16) float sScale1[256];
    __shared__ __align__(16) float sShift1[256];
    int t = threadIdx.x;
    int tx = t & 15, ty = t >> 4;
    int row0 = blockIdx.x * 128;
    ull acc2[8][4] = {};

    // finalize BN1 stats in-block (replaces finalize_kernel launch)
    {
        float mu  = g_stat[t] * invM;
        float msq = g_stat[256 + t] * invM;
        float var = msq - mu * mu;
        float sc = gam[t] * rsqrtf(var + 1e-5f);
        sScale1[t] = sc;
        sShift1[t] = bet[t] - mu * sc;
    }
    if (t < 128) { sSum[t] = 0.f; sSq[t] = 0.f; }
    __syncthreads();

    G2_LOAD(0, 0);
    __syncthreads();
    for (int kt = 0; kt < 256; kt += 16) {
        int cur = (kt >> 4) & 1;
        if (kt + 16 < 256) G2_LOAD(cur ^ 1, kt + 16);
        GEMM_KK(cur);
        __syncthreads();
    }
    float acc[8][8];
#pragma unroll
    for (int i = 0; i < 8; i++)
#pragma unroll
        for (int j2 = 0; j2 < 4; j2++)
            UNPACK2(acc[i][2 * j2], acc[i][2 * j2 + 1], acc2[i][j2]);

    float ls[8] = {}, lq[8] = {};
#pragma unroll
    for (int i = 0; i < 8; i++) {
        int m = row0 + ((i < 4) ? (ty * 4 + i) : (64 + ty * 4 + i - 4));
        if (m >= M) continue;
#pragma unroll
        for (int h = 0; h < 2; h++) {
            int c = h * 64 + tx * 4;
            float4 bb = *(const float4*)(bias + c);
            float4 o;
            o.x = acc[i][h * 4 + 0] + bb.x;
            o.y = acc[i][h * 4 + 1] + bb.y;
            o.z = acc[i][h * 4 + 2] + bb.z;
            o.w = acc[i][h * 4 + 3] + bb.w;
            *(float4*)(out + (size_t)m * 128 + c) = o;
            ls[h*4+0] += o.x; lq[h*4+0] = fmaf(o.x, o.x, lq[h*4+0]);
            ls[h*4+1] += o.y; lq[h*4+1] = fmaf(o.y, o.y, lq[h*4+1]);
            ls[h*4+2] += o.z; lq[h*4+2] = fmaf(o.z, o.z, lq[h*4+2]);
            ls[h*4+3] += o.w; lq[h*4+3] = fmaf(o.w, o.w, lq[h*4+3]);
        }
    }
#pragma unroll
    for (int h = 0; h < 2; h++)
#pragma unroll
        for (int j = 0; j < 4; j++) {
            int c = h * 64 + tx * 4 + j;
            atomicAdd(&sSum[c], ls[h*4+j]);
            atomicAdd(&sSq[c],  lq[h*4+j]);
        }
    __syncthreads();
    if (t < 128) {
        atomicAdd(&g_stat[512 + t], sSum[t]);
        atomicAdd(&g_stat[640 + t], sSq[t]);
    }
}

// ---------------- Threefry-2x32, key = (0, 42) -------------------------------------
__device__ __forceinline__ uint2 threefry2x32_042(uint32_t x0, uint32_t x1)
{
    const uint32_t k0 = 0u, k1 = 42u;
    const uint32_t k2 = k0 ^ k1 ^ 0x1BD11BDAu;
    x0 += k0; x1 += k1;
#define TF_R(r) { x0 += x1; x1 = __funnelshift_l(x1, x1, r); x1 ^= x0; }
    TF_R(13) TF_R(15) TF_R(26) TF_R(6)
    x0 += k1; x1 += k2 + 1u;
    TF_R(17) TF_R(29) TF_R(16) TF_R(24)
    x0 += k2; x1 += k0 + 2u;
    TF_R(13) TF_R(15) TF_R(26) TF_R(6)
    x0 += k0; x1 += k1 + 3u;
    TF_R(17) TF_R(29) TF_R(16) TF_R(24)
    x0 += k1; x1 += k2 + 4u;
    TF_R(13) TF_R(15) TF_R(26) TF_R(6)
    x0 += k2; x1 += k0 + 5u;
#undef TF_R
    return make_uint2(x0, x1);
}

// ---------------- outer BN (finalized in-block) + dropout --------------------------
__global__ __launch_bounds__(256) void bn_dropout_kernel(
    const float* __restrict__ gam, const float* __restrict__ bet,
    float* __restrict__ out, int total, float invM)
{
    __shared__ __align__(16) float sScale2[128];
    __shared__ __align__(16) float sShift2[128];
    int t = threadIdx.x;
    if (t < 128) {
        float mu  = g_stat[512 + t] * invM;
        float msq = g_stat[640 + t] * invM;
        float var = msq - mu * mu;
        float sc = gam[t] * rsqrtf(var + 1e-5f);
        sScale2[t] = sc;
        sShift2[t] = bet[t] - mu * sc;
    }
    __syncthreads();

    int gid = blockIdx.x * blockDim.x + t;
    int i0 = gid * 4;
    if (i0 >= total) return;
    float4 v = *(float4*)(out + i0);
    int c = i0 & 127;
    float4 sc = *(const float4*)(sScale2 + c);
    float4 sh = *(const float4*)(sShift2 + c);
    float vals[4] = { fmaf(v.x, sc.x, sh.x), fmaf(v.y, sc.y, sh.y),
                      fmaf(v.z, sc.z, sh.z), fmaf(v.w, sc.w, sh.w) };
    float res[4];
#pragma unroll
    for (int j = 0; j < 4; j++) {
        uint2 o = threefry2x32_042(0u, (uint32_t)(i0 + j));
        uint32_t bits = o.x ^ o.y;
        float u = __uint_as_float((bits >> 9) | 0x3f800000u) - 1.0f;
        res[j] = (u < 0.8f) ? vals[j] * 1.25f : 0.0f;
    }
    *(float4*)(out + i0) = make_float4(res[0], res[1], res[2], res[3]);
}

// ---------------- launch ------------------------------------------------------------
extern "C" void kernel_launch(void* const* d_in, const int* in_sizes, int n_in,
                              void* d_out, int out_size)
{
    const float* x      = (const float*)d_in[0];
    const void*  ei     = d_in[1];
    const float* ea     = (const float*)d_in[2];
    const float* W_edge = (const float*)d_in[3];
    const float* b_edge = (const float*)d_in[4];
    const float* epsp   = (const float*)d_in[5];
    const float* W1     = (const float*)d_in[6];
    const float* b1     = (const float*)d_in[7];
    const float* g1     = (const float*)d_in[8];
    const float* beta1  = (const float*)d_in[9];
    const float* W2     = (const float*)d_in[10];
    const float* b2     = (const float*)d_in[11];
    const float* g_o    = (const float*)d_in[12];
    const float* beta_o = (const float*)d_in[13];
    float* out = (float*)d_out;

    int M = in_sizes[0] / EMB;     // 50000
    int E = in_sizes[1] / 2;       // 800000
    float invM = 1.0f / (float)M;
    int nScanBlocks = (M + 1023) / 1024;   // 49

    zero_kernel<<<(M + 255) / 256, 256>>>((const unsigned long long*)ei, M);
    hist_kernel<<<(E + 255) / 256, 256>>>(ei, E);
    scan1_kernel<<<nScanBlocks, 256>>>(M);
    scan2_kernel<<<1, 32>>>(nScanBlocks, M);
    scan3_kernel<<<nScanBlocks, 256>>>(M);
    scatter_kernel<<<(E + 255) / 256, 256>>>(ei, E);
    aggr_kernel<<<AGGR_BLOCKS, 256>>>((const float4*)x, ea,
                                      (const float4*)W_edge, (const float4*)b_edge, M);
    int gM = (M + 127) / 128;
    gemm1_kernel<<<dim3(gM, 2), 256>>>(x, W1, b1, epsp, M);
    gemm2_kernel<<<gM, 256>>>(W2, b2, g1, beta1, out, M, invM);
    bn_dropout_kernel<<<(out_size / 4 + 255) / 256, 256>>>(g_o, beta_o, out, out_size, invM);
}

// round 14
// speedup vs baseline: 1.1011x; 1.1011x over previous
#include <cuda_runtime.h>
#include <cstdint>

#define EMB 128
#define NMAX 50000
#define EMAX 800000
#define FULLM 0xffffffffu

typedef unsigned long long ull;

// ---------------- f32x2 packed helpers --------------------------------------------
#define FMA2(d, a, b, c) \
    asm("fma.rn.f32x2 %0, %1, %2, %3;" : "=l"(d) : "l"(a), "l"(b), "l"(c))
#define PACK2(d, x) \
    asm("mov.b64 %0, {%1, %1};" : "=l"(d) : "f"(x))
#define PACKAB(d, x, y) \
    asm("mov.b64 %0, {%1, %2};" : "=l"(d) : "f"(x), "f"(y))
#define UNPACK2(lo, hi, v) \
    asm("mov.b64 {%0, %1}, %2;" : "=f"(lo), "=f"(hi) : "l"(v))

// ---------------- scratch (static device globals; no allocation) ----------------
__device__ float g_aggr[NMAX * EMB];          // 25.6 MB
__device__ float g_h1[NMAX * 2 * EMB];        // 51.2 MB
__device__ float g_stat[768];                 // sum1[256] sq1[256] sum2[128] sq2[128]
__device__ int   g_is64;
__device__ int   g_deg[NMAX];
__device__ int   g_off[NMAX + 1];
__device__ int   g_cur[NMAX];
__device__ int   g_bsum[64];
__device__ uint2 g_elist[EMAX];               // (src, edge_id) sorted by dst

// ---------------- zero counters + stats + detect dtype (merged) -------------------
__global__ void zero_kernel(const unsigned long long* __restrict__ p, int n) {
    int i = blockIdx.x * blockDim.x + threadIdx.x;
    if (i < n) g_deg[i] = 0;
    if (blockIdx.x == 0) {
        for (int j = threadIdx.x; j < 768; j += blockDim.x) g_stat[j] = 0.0f;
        if (threadIdx.x == 0) {
            int ok = 1;
            for (int k = 0; k < 64; k++)
                if (p[k] >= (unsigned long long)n) { ok = 0; break; }
            g_is64 = ok;
        }
    }
}

__device__ __forceinline__ void load_edge(const void* eiv, int e, int E,
                                          int& src, int& dst) {
    if (g_is64) {
        const long long* pe = (const long long*)eiv;
        src = (int)pe[e]; dst = (int)pe[(size_t)E + e];
    } else {
        const int* pe = (const int*)eiv;
        src = pe[e]; dst = pe[(size_t)E + e];
    }
}

// ---------------- CSR build: histogram -------------------------------------------
__global__ void hist_kernel(const void* __restrict__ eiv, int E) {
    int e = blockIdx.x * blockDim.x + threadIdx.x;
    if (e >= E) return;
    int src, dst; load_edge(eiv, e, E, src, dst);
    atomicAdd(&g_deg[dst], 1);
}

// ---------------- scan phase 1: 256 threads x 4 elems (1024/block) ----------------
__global__ __launch_bounds__(256) void scan1_kernel(int n) {
    __shared__ int wsum[8];
    int tid = threadIdx.x;
    int lane = tid & 31, wid = tid >> 5;
    int i0 = blockIdx.x * 1024 + tid * 4;
    int v0 = (i0 + 0 < n) ? g_deg[i0 + 0] : 0;
    int v1 = (i0 + 1 < n) ? g_deg[i0 + 1] : 0;
    int v2 = (i0 + 2 < n) ? g_deg[i0 + 2] : 0;
    int v3 = (i0 + 3 < n) ? g_deg[i0 + 3] : 0;
    int tsum = v0 + v1 + v2 + v3;
    int x = tsum;
#pragma unroll
    for (int off = 1; off < 32; off <<= 1) {
        int t = __shfl_up_sync(FULLM, x, off);
        if (lane >= off) x += t;
    }
    if (lane == 31) wsum[wid] = x;
    __syncthreads();
    if (wid == 0) {
        int s = (lane < 8) ? wsum[lane] : 0;
#pragma unroll
        for (int off = 1; off < 8; off <<= 1) {
            int t = __shfl_up_sync(FULLM, s, off);
            if (lane >= off) s += t;
        }
        if (lane < 8) wsum[lane] = s;
        if (lane == 7) g_bsum[blockIdx.x] = s;
    }
    __syncthreads();
    int wbase = (wid > 0) ? wsum[wid - 1] : 0;
    int excl = wbase + x - tsum;
    if (i0 + 0 < n) g_off[i0 + 0] = excl;         excl += v0;
    if (i0 + 1 < n) g_off[i0 + 1] = excl;         excl += v1;
    if (i0 + 2 < n) g_off[i0 + 2] = excl;         excl += v2;
    if (i0 + 3 < n) g_off[i0 + 3] = excl;
}

// ---------------- scan phase 3 (scan2 folded in): each block scans bsums ----------
__global__ __launch_bounds__(256) void scan3_kernel(int n, int nblocks) {
    __shared__ int s_boff;
    int t = threadIdx.x, lane = t & 31;
    if (t < 32) {
        int v  = (lane < nblocks) ? g_bsum[lane] : 0;
        int x = v;
#pragma unroll
        for (int off = 1; off < 32; off <<= 1) {
            int u = __shfl_up_sync(FULLM, x, off);
            if (lane >= off) x += u;
        }
        int c32 = __shfl_sync(FULLM, x, 31);
        int v2 = (lane + 32 < nblocks) ? g_bsum[lane + 32] : 0;
        int x2 = v2;
#pragma unroll
        for (int off = 1; off < 32; off <<= 1) {
            int u = __shfl_up_sync(FULLM, x2, off);
            if (lane >= off) x2 += u;
        }
        int total = c32 + __shfl_sync(FULLM, x2, 31);
        int b = blockIdx.x;
        int excl_lo = x - v;            // exclusive prefix at lane (first 32)
        int excl_hi = c32 + x2 - v2;    // exclusive prefix at lane+32
        int boff = (b < 32) ? __shfl_sync(FULLM, excl_lo, b)
                            : __shfl_sync(FULLM, excl_hi, b - 32);
        if (lane == 0) {
            s_boff = boff;
            if (b == 0) g_off[n] = total;
        }
    }
    __syncthreads();
    int bo = s_boff;
    int i0 = blockIdx.x * 1024 + t * 4;
#pragma unroll
    for (int q = 0; q < 4; q++) {
        int i = i0 + q;
        if (i < n) {
            int o = g_off[i] + bo;
            g_off[i] = o;
            g_cur[i] = o;
        }
    }
}

// ---------------- CSR build: scatter ----------------------------------------------
__global__ void scatter_kernel(const void* __restrict__ eiv, int E) {
    int e = blockIdx.x * blockDim.x + threadIdx.x;
    if (e >= E) return;
    int src, dst; load_edge(eiv, e, E, src, dst);
    int pos = atomicAdd(&g_cur[dst], 1);
    g_elist[pos] = make_uint2((unsigned)src, (unsigned)e);
}

// ---------------- aggregation: PERSISTENT warps, W in regs, 2-edge FFMA2 ----------
#define AGGR_BLOCKS 296   // 2 blocks per SM on 148 SMs

__global__ __launch_bounds__(256) void aggr_kernel(
    const float4* __restrict__ x4, const float* __restrict__ ea,
    const float4* __restrict__ We4, const float4* __restrict__ be4, int n)
{
    __shared__ float2 s_av[8][32][18];
    int t = threadIdx.x, lane = t & 31, warp = t >> 5;

    ull w01[16], w23[16];
#pragma unroll
    for (int k = 0; k < 16; k++) {
        float4 w = We4[k * 32 + lane];
        PACKAB(w01[k], w.x, w.y);
        PACKAB(w23[k], w.z, w.w);
    }
    float4 bia = be4[lane];
    ull b01, b23;
    PACKAB(b01, bia.x, bia.y);
    PACKAB(b23, bia.z, bia.w);

    int stride = gridDim.x * 8;
    for (int dst = blockIdx.x * 8 + warp; dst < n; dst += stride) {
        int beg = g_off[dst], end = g_off[dst + 1];
        float4 acc = make_float4(0.f, 0.f, 0.f, 0.f);

        for (int b = beg; b < end; b += 32) {
            int cnt = min(32, end - b);
            uint2 se = (lane < cnt) ? g_elist[b + lane] : make_uint2(0u, 0u);
            if (lane < cnt) {
                const float4* pa = (const float4*)(ea + (size_t)se.y * 16);
                float4* dstp = (float4*)&s_av[warp][lane][0];
#pragma unroll
                for (int q = 0; q < 4; q++) {
                    float4 a = pa[q];
                    dstp[q * 2 + 0] = make_float4(a.x, a.x, a.y, a.y);
                    dstp[q * 2 + 1] = make_float4(a.z, a.z, a.w, a.w);
                }
            }
            __syncwarp();
            for (int j = 0; j < cnt; j += 2) {
                int j1 = min(j + 1, cnt - 1);
                bool has1 = (j + 1 < cnt);
                int src0 = __shfl_sync(FULLM, (int)se.x, j);
                int src1 = __shfl_sync(FULLM, (int)se.x, j1);
                float4 xv0 = x4[(size_t)src0 * 32 + lane];
                float4 xv1 = x4[(size_t)src1 * 32 + lane];
                ull ma01 = b01, ma23 = b23, mb01 = b01, mb23 = b23;
                const ull* ap0 = (const ull*)&s_av[warp][j][0];
                const ull* ap1 = (const ull*)&s_av[warp][j1][0];
#pragma unroll
                for (int k = 0; k < 16; k++) {
                    ull v0 = ap0[k];
                    ull v1 = ap1[k];
                    FMA2(ma01, v0, w01[k], ma01);
                    FMA2(ma23, v0, w23[k], ma23);
                    FMA2(mb01, v1, w01[k], mb01);
                    FMA2(mb23, v1, w23[k], mb23);
                }
                float f0, f1, f2, f3;
                UNPACK2(f0, f1, ma01);
                UNPACK2(f2, f3, ma23);
                acc.x += fmaxf(f0 + xv0.x, 0.0f);
                acc.y += fmaxf(f1 + xv0.y, 0.0f);
                acc.z += fmaxf(f2 + xv0.z, 0.0f);
                acc.w += fmaxf(f3 + xv0.w, 0.0f);
                if (has1) {
                    UNPACK2(f0, f1, mb01);
                    UNPACK2(f2, f3, mb23);
                    acc.x += fmaxf(f0 + xv1.x, 0.0f);
                    acc.y += fmaxf(f1 + xv1.y, 0.0f);
                    acc.z += fmaxf(f2 + xv1.z, 0.0f);
                    acc.w += fmaxf(f3 + xv1.w, 0.0f);
                }
            }
            __syncwarp();
        }
        *(float4*)(g_aggr + (size_t)dst * EMB + lane * 4) = acc;
    }
}

// ---------------- GEMM1: h1 = ((1+eps)*x + aggr) @ W1 + b1, dbuf + FFMA2 + stats --
#define G1_LOAD(buf, kt) do {                                                       \
    _Pragma("unroll")                                                               \
    for (int l = 0; l < 2; l++) {                                                   \
        int f = t + l * 256;                                                        \
        int r = f >> 2, kq = (f & 3) * 4;                                           \
        int m = row0 + r;                                                           \
        float4 v = make_float4(0.f, 0.f, 0.f, 0.f);                                 \
        if (m < M) {                                                                \
            float4 xv = *(const float4*)(X + (size_t)m * 128 + (kt) + kq);          \
            float4 av = *(const float4*)(g_aggr + (size_t)m * 128 + (kt) + kq);     \
            v.x = fmaf(eps1, xv.x, av.x);                                           \
            v.y = fmaf(eps1, xv.y, av.y);                                           \
            v.z = fmaf(eps1, xv.z, av.z);                                           \
            v.w = fmaf(eps1, xv.w, av.w);                                           \
        }                                                                           \
        As[buf][kq + 0][r] = v.x; As[buf][kq + 1][r] = v.y;                         \
        As[buf][kq + 2][r] = v.z; As[buf][kq + 3][r] = v.w;                         \
    }                                                                               \
    _Pragma("unroll")                                                               \
    for (int l = 0; l < 2; l++) {                                                   \
        int f = t + l * 256;                                                        \
        int kr = f >> 5, nc = (f & 31) * 4;                                         \
        *(float4*)&Bs[buf][kr][nc] =                                                \
            *(const float4*)(W + (size_t)((kt) + kr) * 256 + col0 + nc);            \
    }                                                                               \
} while (0)

#define GEMM_KK(cur) do {                                                           \
    _Pragma("unroll")                                                               \
    for (int kk = 0; kk < 16; kk++) {                                               \
        float a0[8], b0[8];                                                         \
        *(float4*)(a0)     = *(const float4*)&As[cur][kk][ty * 4];                  \
        *(float4*)(a0 + 4) = *(const float4*)&As[cur][kk][64 + ty * 4];             \
        *(float4*)(b0)     = *(const float4*)&Bs[cur][kk][tx * 4];                  \
        *(float4*)(b0 + 4) = *(const float4*)&Bs[cur][kk][64 + tx * 4];             \
        ull bp[4], ap[8];                                                           \
        _Pragma("unroll")                                                           \
        for (int j2 = 0; j2 < 4; j2++) PACKAB(bp[j2], b0[2 * j2], b0[2 * j2 + 1]);  \
        _Pragma("unroll")                                                           \
        for (int i = 0; i < 8; i++) PACK2(ap[i], a0[i]);                            \
        _Pragma("unroll")                                                           \
        for (int i = 0; i < 8; i++)                                                 \
            _Pragma("unroll")                                                       \
            for (int j2 = 0; j2 < 4; j2++)                                          \
                FMA2(acc2[i][j2], ap[i], bp[j2], acc2[i][j2]);                      \
    }                                                                               \
} while (0)

__global__ __launch_bounds__(256, 2) void gemm1_kernel(
    const float* __restrict__ X, const float* __restrict__ W,
    const float* __restrict__ bias, const float* __restrict__ epsp, int M)
{
    __shared__ float As[2][16][132];
    __shared__ float Bs[2][16][132];
    __shared__ float sSum[128], sSq[128];
    const float eps1 = 1.0f + *epsp;
    int t = threadIdx.x;
    int tx = t & 15, ty = t >> 4;
    int row0 = blockIdx.x * 128;
    int col0 = blockIdx.y * 128;
    ull acc2[8][4] = {};

    if (t < 128) { sSum[t] = 0.f; sSq[t] = 0.f; }
    G1_LOAD(0, 0);
    __syncthreads();
    for (int kt = 0; kt < 128; kt += 16) {
        int cur = (kt >> 4) & 1;
        if (kt + 16 < 128) G1_LOAD(cur ^ 1, kt + 16);
        GEMM_KK(cur);
        __syncthreads();
    }
    float acc[8][8];
#pragma unroll
    for (int i = 0; i < 8; i++)
#pragma unroll
        for (int j2 = 0; j2 < 4; j2++)
            UNPACK2(acc[i][2 * j2], acc[i][2 * j2 + 1], acc2[i][j2]);

    float ls[8] = {}, lq[8] = {};
#pragma unroll
    for (int i = 0; i < 8; i++) {
        int m = row0 + ((i < 4) ? (ty * 4 + i) : (64 + ty * 4 + i - 4));
        if (m >= M) continue;
#pragma unroll
        for (int h = 0; h < 2; h++) {
            int c = col0 + h * 64 + tx * 4;
            float4 bb = *(const float4*)(bias + c);
            float4 o;
            o.x = acc[i][h * 4 + 0] + bb.x;
            o.y = acc[i][h * 4 + 1] + bb.y;
            o.z = acc[i][h * 4 + 2] + bb.z;
            o.w = acc[i][h * 4 + 3] + bb.w;
            *(float4*)(g_h1 + (size_t)m * 256 + c) = o;
            ls[h*4+0] += o.x; lq[h*4+0] = fmaf(o.x, o.x, lq[h*4+0]);
            ls[h*4+1] += o.y; lq[h*4+1] = fmaf(o.y, o.y, lq[h*4+1]);
            ls[h*4+2] += o.z; lq[h*4+2] = fmaf(o.z, o.z, lq[h*4+2]);
            ls[h*4+3] += o.w; lq[h*4+3] = fmaf(o.w, o.w, lq[h*4+3]);
        }
    }
#pragma unroll
    for (int h = 0; h < 2; h++)
#pragma unroll
        for (int j = 0; j < 4; j++) {
            int c = h * 64 + tx * 4 + j;
            atomicAdd(&sSum[c], ls[h*4+j]);
            atomicAdd(&sSq[c],  lq[h*4+j]);
        }
    __syncthreads();
    if (t < 128) {
        atomicAdd(&g_stat[col0 + t],       sSum[t]);
        atomicAdd(&g_stat[256 + col0 + t], sSq[t]);
    }
}

// ---------------- GEMM2: BN1 scale/shift computed per block, + fused stats --------
#define G2_LOAD(buf, kt) do {                                                       \
    _Pragma("unroll")                                                               \
    for (int l = 0; l < 2; l++) {                                                   \
        int f = t + l * 256;                                                        \
        int r = f >> 2, kq = (f & 3) * 4;                                           \
        int m = row0 + r;                                                           \
        float4 v = make_float4(0.f, 0.f, 0.f, 0.f);                                 \
        if (m < M) {                                                                \
            float4 hv = *(const float4*)(g_h1 + (size_t)m * 256 + (kt) + kq);       \
            float4 sc = *(const float4*)(sScale1 + (kt) + kq);                      \
            float4 sh = *(const float4*)(sShift1 + (kt) + kq);                      \
            v.x = fmaxf(fmaf(hv.x, sc.x, sh.x), 0.0f);                              \
            v.y = fmaxf(fmaf(hv.y, sc.y, sh.y), 0.0f);                              \
            v.z = fmaxf(fmaf(hv.z, sc.z, sh.z), 0.0f);                              \
            v.w = fmaxf(fmaf(hv.w, sc.w, sh.w), 0.0f);                              \
        }                                                                           \
        As[buf][kq + 0][r] = v.x; As[buf][kq + 1][r] = v.y;                         \
        As[buf][kq + 2][r] = v.z; As[buf][kq + 3][r] = v.w;                         \
    }                                                                               \
    _Pragma("unroll")                                                               \
    for (int l = 0; l < 2; l++) {                                                   \
        int f = t + l * 256;                                                        \
        int kr = f >> 5, nc = (f & 31) * 4;                                         \
        *(float4*)&Bs[buf][kr][nc] =                                                \
            *(const float4*)(W + (size_t)((kt) + kr) * 128 + nc);                   \
    }                                                                               \
} while (0)

__global__ __launch_bounds__(256, 2) void gemm2_kernel(
    const float* __restrict__ W, const float* __restrict__ bias,
    const float* __restrict__ gam, const float* __restrict__ bet,
    float* __restrict__ out, int M, float invM)
{
    __shared__ float As[2][16][132];
    __shared__ float Bs[2][16][132];
    __shared__ float sSum[128], sSq[128];
    __shared__ __align__(16) float sScale1[256];
    __shared__ __align__(16) float sShift1[256];
    int t = threadIdx.x;
    int tx = t & 15, ty = t >> 4;
    int row0 = blockIdx.x * 128;
    ull acc2[8][4] = {};

    {
        float mu  = g_stat[t] * invM;
        float msq = g_stat[256 + t] * invM;
        float var = msq - mu * mu;
        float sc = gam[t] * rsqrtf(var + 1e-5f);
        sScale1[t] = sc;
        sShift1[t] = bet[t] - mu * sc;
    }
    if (t < 128) { sSum[t] = 0.f; sSq[t] = 0.f; }
    __syncthreads();

    G2_LOAD(0, 0);
    __syncthreads();
    for (int kt = 0; kt < 256; kt += 16) {
        int cur = (kt >> 4) & 1;
        if (kt + 16 < 256) G2_LOAD(cur ^ 1, kt + 16);
        GEMM_KK(cur);
        __syncthreads();
    }
    float acc[8][8];
#pragma unroll
    for (int i = 0; i < 8; i++)
#pragma unroll
        for (int j2 = 0; j2 < 4; j2++)
            UNPACK2(acc[i][2 * j2], acc[i][2 * j2 + 1], acc2[i][j2]);

    float ls[8] = {}, lq[8] = {};
#pragma unroll
    for (int i = 0; i < 8; i++) {
        int m = row0 + ((i < 4) ? (ty * 4 + i) : (64 + ty * 4 + i - 4));
        if (m >= M) continue;
#pragma unroll
        for (int h = 0; h < 2; h++) {
            int c = h * 64 + tx * 4;
            float4 bb = *(const float4*)(bias + c);
            float4 o;
            o.x = acc[i][h * 4 + 0] + bb.x;
            o.y = acc[i][h * 4 + 1] + bb.y;
            o.z = acc[i][h * 4 + 2] + bb.z;
            o.w = acc[i][h * 4 + 3] + bb.w;
            *(float4*)(out + (size_t)m * 128 + c) = o;
            ls[h*4+0] += o.x; lq[h*4+0] = fmaf(o.x, o.x, lq[h*4+0]);
            ls[h*4+1] += o.y; lq[h*4+1] = fmaf(o.y, o.y, lq[h*4+1]);
            ls[h*4+2] += o.z; lq[h*4+2] = fmaf(o.z, o.z, lq[h*4+2]);
            ls[h*4+3] += o.w; lq[h*4+3] = fmaf(o.w, o.w, lq[h*4+3]);
        }
    }
#pragma unroll
    for (int h = 0; h < 2; h++)
#pragma unroll
        for (int j = 0; j < 4; j++) {
            int c = h * 64 + tx * 4 + j;
            atomicAdd(&sSum[c], ls[h*4+j]);
            atomicAdd(&sSq[c],  lq[h*4+j]);
        }
    __syncthreads();
    if (t < 128) {
        atomicAdd(&g_stat[512 + t], sSum[t]);
        atomicAdd(&g_stat[640 + t], sSq[t]);
    }
}

// ---------------- Threefry-2x32, key = (0, 42) -------------------------------------
__device__ __forceinline__ uint2 threefry2x32_042(uint32_t x0, uint32_t x1)
{
    const uint32_t k0 = 0u, k1 = 42u;
    const uint32_t k2 = k0 ^ k1 ^ 0x1BD11BDAu;
    x0 += k0; x1 += k1;
#define TF_R(r) { x0 += x1; x1 = __funnelshift_l(x1, x1, r); x1 ^= x0; }
    TF_R(13) TF_R(15) TF_R(26) TF_R(6)
    x0 += k1; x1 += k2 + 1u;
    TF_R(17) TF_R(29) TF_R(16) TF_R(24)
    x0 += k2; x1 += k0 + 2u;
    TF_R(13) TF_R(15) TF_R(26) TF_R(6)
    x0 += k0; x1 += k1 + 3u;
    TF_R(17) TF_R(29) TF_R(16) TF_R(24)
    x0 += k1; x1 += k2 + 4u;
    TF_R(13) TF_R(15) TF_R(26) TF_R(6)
    x0 += k2; x1 += k0 + 5u;
#undef TF_R
    return make_uint2(x0, x1);
}

// ---------------- outer BN (finalized in-block) + dropout --------------------------
__global__ __launch_bounds__(256) void bn_dropout_kernel(
    const float* __restrict__ gam, const float* __restrict__ bet,
    float* __restrict__ out, int total, float invM)
{
    __shared__ __align__(16) float sScale2[128];
    __shared__ __align__(16) float sShift2[128];
    int t = threadIdx.x;
    if (t < 128) {
        float mu  = g_stat[512 + t] * invM;
        float msq = g_stat[640 + t] * invM;
        float var = msq - mu * mu;
        float sc = gam[t] * rsqrtf(var + 1e-5f);
        sScale2[t] = sc;
        sShift2[t] = bet[t] - mu * sc;
    }
    __syncthreads();

    int gid = blockIdx.x * blockDim.x + t;
    int i0 = gid * 4;
    if (i0 >= total) return;
    float4 v = *(float4*)(out + i0);
    int c = i0 & 127;
    float4 sc = *(const float4*)(sScale2 + c);
    float4 sh = *(const float4*)(sShift2 + c);
    float vals[4] = { fmaf(v.x, sc.x, sh.x), fmaf(v.y, sc.y, sh.y),
                      fmaf(v.z, sc.z, sh.z), fmaf(v.w, sc.w, sh.w) };
    float res[4];
#pragma unroll
    for (int j = 0; j < 4; j++) {
        uint2 o = threefry2x32_042(0u, (uint32_t)(i0 + j));
        uint32_t bits = o.x ^ o.y;
        float u = __uint_as_float((bits >> 9) | 0x3f800000u) - 1.0f;
        res[j] = (u < 0.8f) ? vals[j] * 1.25f : 0.0f;
    }
    *(float4*)(out + i0) = make_float4(res[0], res[1], res[2], res[3]);
}

// ---------------- launch ------------------------------------------------------------
extern "C" void kernel_launch(void* const* d_in, const int* in_sizes, int n_in,
                              void* d_out, int out_size)
{
    const float* x      = (const float*)d_in[0];
    const void*  ei     = d_in[1];
    const float* ea     = (const float*)d_in[2];
    const float* W_edge = (const float*)d_in[3];
    const float* b_edge = (const float*)d_in[4];
    const float* epsp   = (const float*)d_in[5];
    const float* W1     = (const float*)d_in[6];
    const float* b1     = (const float*)d_in[7];
    const float* g1     = (const float*)d_in[8];
    const float* beta1  = (const float*)d_in[9];
    const float* W2     = (const float*)d_in[10];
    const float* b2     = (const float*)d_in[11];
    const float* g_o    = (const float*)d_in[12];
    const float* beta_o = (const float*)d_in[13];
    float* out = (float*)d_out;

    int M = in_sizes[0] / EMB;     // 50000
    int E = in_sizes[1] / 2;       // 800000
    float invM = 1.0f / (float)M;
    int nScanBlocks = (M + 1023) / 1024;   // 49

    zero_kernel<<<(M + 255) / 256, 256>>>((const unsigned long long*)ei, M);
    hist_kernel<<<(E + 255) / 256, 256>>>(ei, E);
    scan1_kernel<<<nScanBlocks, 256>>>(M);
    scan3_kernel<<<nScanBlocks, 256>>>(M, nScanBlocks);
    scatter_kernel<<<(E + 255) / 256, 256>>>(ei, E);
    aggr_kernel<<<AGGR_BLOCKS, 256>>>((const float4*)x, ea,
                                      (const float4*)W_edge, (const float4*)b_edge, M);
    int gM = (M + 127) / 128;
    gemm1_kernel<<<dim3(gM, 2), 256>>>(x, W1, b1, epsp, M);
    gemm2_kernel<<<gM, 256>>>(W2, b2, g1, beta1, out, M, invM);
    bn_dropout_kernel<<<(out_size / 4 + 255) / 256, 256>>>(g_o, beta_o, out, out_size, invM);
}

// round 15
// speedup vs baseline: 1.1058x; 1.0043x over previous
#include <cuda_runtime.h>
#include <cstdint>

#define EMB 128
#define NMAX 50000
#define EMAX 800000
#define FULLM 0xffffffffu

typedef unsigned long long ull;

// ---------------- f32x2 packed helpers --------------------------------------------
#define FMA2(d, a, b, c) \
    asm("fma.rn.f32x2 %0, %1, %2, %3;" : "=l"(d) : "l"(a), "l"(b), "l"(c))
#define PACK2(d, x) \
    asm("mov.b64 %0, {%1, %1};" : "=l"(d) : "f"(x))
#define PACKAB(d, x, y) \
    asm("mov.b64 %0, {%1, %2};" : "=l"(d) : "f"(x), "f"(y))
#define UNPACK2(lo, hi, v) \
    asm("mov.b64 {%0, %1}, %2;" : "=f"(lo), "=f"(hi) : "l"(v))

// ---------------- scratch (static device globals; no allocation) ----------------
__device__ float g_aggr[NMAX * EMB];          // 25.6 MB
__device__ float g_h1[NMAX * 2 * EMB];        // 51.2 MB
__device__ float g_stat[768];                 // sum1[256] sq1[256] sum2[128] sq2[128]
__device__ int   g_is64;
__device__ int   g_deg[NMAX];                 // zero-initialized at load; re-zeroed by scan1
__device__ int   g_off[NMAX + 1];
__device__ int   g_cur[NMAX];
__device__ int   g_bsum[64];
__device__ uint2 g_elist[EMAX];               // (src, edge_id) sorted by dst

// ---------------- detect helper (per-block, race-free) -----------------------------
__device__ __forceinline__ int detect_is64(const unsigned long long* p, int n) {
    int ok = 1;
#pragma unroll 8
    for (int k = 0; k < 64; k++)
        if (p[k] >= (unsigned long long)n) { ok = 0; break; }
    return ok;
}

// ---------------- CSR build: histogram (+ g_stat zero + detect publish) ------------
__global__ void hist_kernel(const void* __restrict__ eiv, int E, int n_nodes) {
    __shared__ int s_is64;
    int t = threadIdx.x;
    if (t == 0) {
        int ok = detect_is64((const unsigned long long*)eiv, n_nodes);
        s_is64 = ok;
        if (blockIdx.x == 0) g_is64 = ok;   // publish for later kernels
    }
    __syncthreads();
    if (blockIdx.x == 0) {
        for (int j = t; j < 768; j += blockDim.x) g_stat[j] = 0.0f;
    }
    int e = blockIdx.x * blockDim.x + t;
    if (e >= E) return;
    int dst;
    if (s_is64) {
        const long long* pe = (const long long*)eiv;
        dst = (int)pe[(size_t)E + e];
    } else {
        const int* pe = (const int*)eiv;
        dst = pe[(size_t)E + e];
    }
    atomicAdd(&g_deg[dst], 1);
}

__device__ __forceinline__ void load_edge(const void* eiv, int e, int E,
                                          int& src, int& dst) {
    if (g_is64) {
        const long long* pe = (const long long*)eiv;
        src = (int)pe[e]; dst = (int)pe[(size_t)E + e];
    } else {
        const int* pe = (const int*)eiv;
        src = pe[e]; dst = pe[(size_t)E + e];
    }
}

// ---------------- scan phase 1: 256 threads x 4 elems; re-zeroes g_deg -------------
__global__ __launch_bounds__(256) void scan1_kernel(int n) {
    __shared__ int wsum[8];
    int tid = threadIdx.x;
    int lane = tid & 31, wid = tid >> 5;
    int i0 = blockIdx.x * 1024 + tid * 4;
    int v0 = (i0 + 0 < n) ? g_deg[i0 + 0] : 0;
    int v1 = (i0 + 1 < n) ? g_deg[i0 + 1] : 0;
    int v2 = (i0 + 2 < n) ? g_deg[i0 + 2] : 0;
    int v3 = (i0 + 3 < n) ? g_deg[i0 + 3] : 0;
    // re-zero for the next replay (graph-capturable reset)
    if (i0 + 3 < n) {
        *(int4*)(g_deg + i0) = make_int4(0, 0, 0, 0);
    } else {
        if (i0 + 0 < n) g_deg[i0 + 0] = 0;
        if (i0 + 1 < n) g_deg[i0 + 1] = 0;
        if (i0 + 2 < n) g_deg[i0 + 2] = 0;
    }
    int tsum = v0 + v1 + v2 + v3;
    int x = tsum;
#pragma unroll
    for (int off = 1; off < 32; off <<= 1) {
        int t = __shfl_up_sync(FULLM, x, off);
        if (lane >= off) x += t;
    }
    if (lane == 31) wsum[wid] = x;
    __syncthreads();
    if (wid == 0) {
        int s = (lane < 8) ? wsum[lane] : 0;
#pragma unroll
        for (int off = 1; off < 8; off <<= 1) {
            int t = __shfl_up_sync(FULLM, s, off);
            if (lane >= off) s += t;
        }
        if (lane < 8) wsum[lane] = s;
        if (lane == 7) g_bsum[blockIdx.x] = s;
    }
    __syncthreads();
    int wbase = (wid > 0) ? wsum[wid - 1] : 0;
    int excl = wbase + x - tsum;
    if (i0 + 0 < n) g_off[i0 + 0] = excl;         excl += v0;
    if (i0 + 1 < n) g_off[i0 + 1] = excl;         excl += v1;
    if (i0 + 2 < n) g_off[i0 + 2] = excl;         excl += v2;
    if (i0 + 3 < n) g_off[i0 + 3] = excl;
}

// ---------------- scan phase 3 (scan2 folded in): each block scans bsums -----------
__global__ __launch_bounds__(256) void scan3_kernel(int n, int nblocks) {
    __shared__ int s_boff;
    int t = threadIdx.x, lane = t & 31;
    if (t < 32) {
        int v  = (lane < nblocks) ? g_bsum[lane] : 0;
        int x = v;
#pragma unroll
        for (int off = 1; off < 32; off <<= 1) {
            int u = __shfl_up_sync(FULLM, x, off);
            if (lane >= off) x += u;
        }
        int c32 = __shfl_sync(FULLM, x, 31);
        int v2 = (lane + 32 < nblocks) ? g_bsum[lane + 32] : 0;
        int x2 = v2;
#pragma unroll
        for (int off = 1; off < 32; off <<= 1) {
            int u = __shfl_up_sync(FULLM, x2, off);
            if (lane >= off) x2 += u;
        }
        int total = c32 + __shfl_sync(FULLM, x2, 31);
        int b = blockIdx.x;
        int excl_lo = x - v;
        int excl_hi = c32 + x2 - v2;
        int boff = (b < 32) ? __shfl_sync(FULLM, excl_lo, b)
                            : __shfl_sync(FULLM, excl_hi, b - 32);
        if (lane == 0) {
            s_boff = boff;
            if (b == 0) g_off[n] = total;
        }
    }
    __syncthreads();
    int bo = s_boff;
    int i0 = blockIdx.x * 1024 + t * 4;
#pragma unroll
    for (int q = 0; q < 4; q++) {
        int i = i0 + q;
        if (i < n) {
            int o = g_off[i] + bo;
            g_off[i] = o;
            g_cur[i] = o;
        }
    }
}

// ---------------- CSR build: scatter ------------------------------------------------
__global__ void scatter_kernel(const void* __restrict__ eiv, int E) {
    int e = blockIdx.x * blockDim.x + threadIdx.x;
    if (e >= E) return;
    int src, dst; load_edge(eiv, e, E, src, dst);
    int pos = atomicAdd(&g_cur[dst], 1);
    g_elist[pos] = make_uint2((unsigned)src, (unsigned)e);
}

// ---------------- aggregation: PERSISTENT warps, W in regs, 2-edge FFMA2 -----------
#define AGGR_BLOCKS 296   // 2 blocks per SM on 148 SMs

__global__ __launch_bounds__(256) void aggr_kernel(
    const float4* __restrict__ x4, const float* __restrict__ ea,
    const float4* __restrict__ We4, const float4* __restrict__ be4, int n)
{
    __shared__ float2 s_av[8][32][18];
    int t = threadIdx.x, lane = t & 31, warp = t >> 5;

    ull w01[16], w23[16];
#pragma unroll
    for (int k = 0; k < 16; k++) {
        float4 w = We4[k * 32 + lane];
        PACKAB(w01[k], w.x, w.y);
        PACKAB(w23[k], w.z, w.w);
    }
    float4 bia = be4[lane];
    ull b01, b23;
    PACKAB(b01, bia.x, bia.y);
    PACKAB(b23, bia.z, bia.w);

    int stride = gridDim.x * 8;
    for (int dst = blockIdx.x * 8 + warp; dst < n; dst += stride) {
        int beg = g_off[dst], end = g_off[dst + 1];
        float4 acc = make_float4(0.f, 0.f, 0.f, 0.f);

        for (int b = beg; b < end; b += 32) {
            int cnt = min(32, end - b);
            uint2 se = (lane < cnt) ? g_elist[b + lane] : make_uint2(0u, 0u);
            if (lane < cnt) {
                const float4* pa = (const float4*)(ea + (size_t)se.y * 16);
                float4* dstp = (float4*)&s_av[warp][lane][0];
#pragma unroll
                for (int q = 0; q < 4; q++) {
                    float4 a = pa[q];
                    dstp[q * 2 + 0] = make_float4(a.x, a.x, a.y, a.y);
                    dstp[q * 2 + 1] = make_float4(a.z, a.z, a.w, a.w);
                }
            }
            __syncwarp();
            for (int j = 0; j < cnt; j += 2) {
                int j1 = min(j + 1, cnt - 1);
                bool has1 = (j + 1 < cnt);
                int src0 = __shfl_sync(FULLM, (int)se.x, j);
                int src1 = __shfl_sync(FULLM, (int)se.x, j1);
                float4 xv0 = x4[(size_t)src0 * 32 + lane];
                float4 xv1 = x4[(size_t)src1 * 32 + lane];
                ull ma01 = b01, ma23 = b23, mb01 = b01, mb23 = b23;
                const ull* ap0 = (const ull*)&s_av[warp][j][0];
                const ull* ap1 = (const ull*)&s_av[warp][j1][0];
#pragma unroll
                for (int k = 0; k < 16; k++) {
                    ull v0 = ap0[k];
                    ull v1 = ap1[k];
                    FMA2(ma01, v0, w01[k], ma01);
                    FMA2(ma23, v0, w23[k], ma23);
                    FMA2(mb01, v1, w01[k], mb01);
                    FMA2(mb23, v1, w23[k], mb23);
                }
                float f0, f1, f2, f3;
                UNPACK2(f0, f1, ma01);
                UNPACK2(f2, f3, ma23);
                acc.x += fmaxf(f0 + xv0.x, 0.0f);
                acc.y += fmaxf(f1 + xv0.y, 0.0f);
                acc.z += fmaxf(f2 + xv0.z, 0.0f);
                acc.w += fmaxf(f3 + xv0.w, 0.0f);
                if (has1) {
                    UNPACK2(f0, f1, mb01);
                    UNPACK2(f2, f3, mb23);
                    acc.x += fmaxf(f0 + xv1.x, 0.0f);
                    acc.y += fmaxf(f1 + xv1.y, 0.0f);
                    acc.z += fmaxf(f2 + xv1.z, 0.0f);
                    acc.w += fmaxf(f3 + xv1.w, 0.0f);
                }
            }
            __syncwarp();
        }
        *(float4*)(g_aggr + (size_t)dst * EMB + lane * 4) = acc;
    }
}

// ---------------- GEMM1: h1 = ((1+eps)*x + aggr) @ W1 + b1, dbuf + FFMA2 + stats ---
#define G1_LOAD(buf, kt) do {                                                       \
    _Pragma("unroll")                                                               \
    for (int l = 0; l < 2; l++) {                                                   \
        int f = t + l * 256;                                                        \
        int r = f >> 2, kq = (f & 3) * 4;                                           \
        int m = row0 + r;                                                           \
        float4 v = make_float4(0.f, 0.f, 0.f, 0.f);                                 \
        if (m < M) {                                                                \
            float4 xv = *(const float4*)(X + (size_t)m * 128 + (kt) + kq);          \
            float4 av = *(const float4*)(g_aggr + (size_t)m * 128 + (kt) + kq);     \
            v.x = fmaf(eps1, xv.x, av.x);                                           \
            v.y = fmaf(eps1, xv.y, av.y);                                           \
            v.z = fmaf(eps1, xv.z, av.z);                                           \
            v.w = fmaf(eps1, xv.w, av.w);                                           \
        }                                                                           \
        As[buf][kq + 0][r] = v.x; As[buf][kq + 1][r] = v.y;                         \
        As[buf][kq + 2][r] = v.z; As[buf][kq + 3][r] = v.w;                         \
    }                                                                               \
    _Pragma("unroll")                                                               \
    for (int l = 0; l < 2; l++) {                                                   \
        int f = t + l * 256;                                                        \
        int kr = f >> 5, nc = (f & 31) * 4;                                         \
        *(float4*)&Bs[buf][kr][nc] =                                                \
            *(const float4*)(W + (size_t)((kt) + kr) * 256 + col0 + nc);            \
    }                                                                               \
} while (0)

#define GEMM_KK(cur) do {                                                           \
    _Pragma("unroll")                                                               \
    for (int kk = 0; kk < 16; kk++) {                                               \
        float a0[8], b0[8];                                                         \
        *(float4*)(a0)     = *(const float4*)&As[cur][kk][ty * 4];                  \
        *(float4*)(a0 + 4) = *(const float4*)&As[cur][kk][64 + ty * 4];             \
        *(float4*)(b0)     = *(const float4*)&Bs[cur][kk][tx * 4];                  \
        *(float4*)(b0 + 4) = *(const float4*)&Bs[cur][kk][64 + tx * 4];             \
        ull bp[4], ap[8];                                                           \
        _Pragma("unroll")                                                           \
        for (int j2 = 0; j2 < 4; j2++) PACKAB(bp[j2], b0[2 * j2], b0[2 * j2 + 1]);  \
        _Pragma("unroll")                                                           \
        for (int i = 0; i < 8; i++) PACK2(ap[i], a0[i]);                            \
        _Pragma("unroll")                                                           \
        for (int i = 0; i < 8; i++)                                                 \
            _Pragma("unroll")                                                       \
            for (int j2 = 0; j2 < 4; j2++)                                          \
                FMA2(acc2[i][j2], ap[i], bp[j2], acc2[i][j2]);                      \
    }                                                                               \
} while (0)

__global__ __launch_bounds__(256, 2) void gemm1_kernel(
    const float* __restrict__ X, const float* __restrict__ W,
    const float* __restrict__ bias, const float* __restrict__ epsp, int M)
{
    __shared__ float As[2][16][132];
    __shared__ float Bs[2][16][132];
    __shared__ float sSum[128], sSq[128];
    const float eps1 = 1.0f + *epsp;
    int t = threadIdx.x;
    int tx = t & 15, ty = t >> 4;
    int row0 = blockIdx.x * 128;
    int col0 = blockIdx.y * 128;
    ull acc2[8][4] = {};

    if (t < 128) { sSum[t] = 0.f; sSq[t] = 0.f; }
    G1_LOAD(0, 0);
    __syncthreads();
    for (int kt = 0; kt < 128; kt += 16) {
        int cur = (kt >> 4) & 1;
        if (kt + 16 < 128) G1_LOAD(cur ^ 1, kt + 16);
        GEMM_KK(cur);
        __syncthreads();
    }
    float acc[8][8];
#pragma unroll
    for (int i = 0; i < 8; i++)
#pragma unroll
        for (int j2 = 0; j2 < 4; j2++)
            UNPACK2(acc[i][2 * j2], acc[i][2 * j2 + 1], acc2[i][j2]);

    float ls[8] = {}, lq[8] = {};
#pragma unroll
    for (int i = 0; i < 8; i++) {
        int m = row0 + ((i < 4) ? (ty * 4 + i) : (64 + ty * 4 + i - 4));
        if (m >= M) continue;
#pragma unroll
        for (int h = 0; h < 2; h++) {
            int c = col0 + h * 64 + tx * 4;
            float4 bb = *(const float4*)(bias + c);
            float4 o;
            o.x = acc[i][h * 4 + 0] + bb.x;
            o.y = acc[i][h * 4 + 1] + bb.y;
            o.z = acc[i][h * 4 + 2] + bb.z;
            o.w = acc[i][h * 4 + 3] + bb.w;
            *(float4*)(g_h1 + (size_t)m * 256 + c) = o;
            ls[h*4+0] += o.x; lq[h*4+0] = fmaf(o.x, o.x, lq[h*4+0]);
            ls[h*4+1] += o.y; lq[h*4+1] = fmaf(o.y, o.y, lq[h*4+1]);
            ls[h*4+2] += o.z; lq[h*4+2] = fmaf(o.z, o.z, lq[h*4+2]);
            ls[h*4+3] += o.w; lq[h*4+3] = fmaf(o.w, o.w, lq[h*4+3]);
        }
    }
#pragma unroll
    for (int h = 0; h < 2; h++)
#pragma unroll
        for (int j = 0; j < 4; j++) {
            int c = h * 64 + tx * 4 + j;
            atomicAdd(&sSum[c], ls[h*4+j]);
            atomicAdd(&sSq[c],  lq[h*4+j]);
        }
    __syncthreads();
    if (t < 128) {
        atomicAdd(&g_stat[col0 + t],       sSum[t]);
        atomicAdd(&g_stat[256 + col0 + t], sSq[t]);
    }
}

// ---------------- GEMM2: BN1 scale/shift computed per block, + fused stats ---------
#define G2_LOAD(buf, kt) do {                                                       \
    _Pragma("unroll")                                                               \
    for (int l = 0; l < 2; l++) {                                                   \
        int f = t + l * 256;                                                        \
        int r = f >> 2, kq = (f & 3) * 4;                                           \
        int m = row0 + r;                                                           \
        float4 v = make_float4(0.f, 0.f, 0.f, 0.f);                                 \
        if (m < M) {                                                                \
            float4 hv = *(const float4*)(g_h1 + (size_t)m * 256 + (kt) + kq);       \
            float4 sc = *(const float4*)(sScale1 + (kt) + kq);                      \
            float4 sh = *(const float4*)(sShift1 + (kt) + kq);                      \
            v.x = fmaxf(fmaf(hv.x, sc.x, sh.x), 0.0f);                              \
            v.y = fmaxf(fmaf(hv.y, sc.y, sh.y), 0.0f);                              \
            v.z = fmaxf(fmaf(hv.z, sc.z, sh.z), 0.0f);                              \
            v.w = fmaxf(fmaf(hv.w, sc.w, sh.w), 0.0f);                              \
        }                                                                           \
        As[buf][kq + 0][r] = v.x; As[buf][kq + 1][r] = v.y;                         \
        As[buf][kq + 2][r] = v.z; As[buf][kq + 3][r] = v.w;                         \
    }                                                                               \
    _Pragma("unroll")                                                               \
    for (int l = 0; l < 2; l++) {                                                   \
        int f = t + l * 256;                                                        \
        int kr = f >> 5, nc = (f & 31) * 4;                                         \
        *(float4*)&Bs[buf][kr][nc] =                                                \
            *(const float4*)(W + (size_t)((kt) + kr) * 128 + nc);                   \
    }                                                                               \
} while (0)

__global__ __launch_bounds__(256, 2) void gemm2_kernel(
    const float* __restrict__ W, const float* __restrict__ bias,
    const float* __restrict__ gam, const float* __restrict__ bet,
    float* __restrict__ out, int M, float invM)
{
    __shared__ float As[2][16][132];
    __shared__ float Bs[2][16][132];
    __shared__ float sSum[128], sSq[128];
    __shared__ __align__(16) float sScale1[256];
    __shared__ __align__(16) float sShift1[256];
    int t = threadIdx.x;
    int tx = t & 15, ty = t >> 4;
    int row0 = blockIdx.x * 128;
    ull acc2[8][4] = {};

    {
        float mu  = g_stat[t] * invM;
        float msq = g_stat[256 + t] * invM;
        float var = msq - mu * mu;
        float sc = gam[t] * rsqrtf(var + 1e-5f);
        sScale1[t] = sc;
        sShift1[t] = bet[t] - mu * sc;
    }
    if (t < 128) { sSum[t] = 0.f; sSq[t] = 0.f; }
    __syncthreads();

    G2_LOAD(0, 0);
    __syncthreads();
    for (int kt = 0; kt < 256; kt += 16) {
        int cur = (kt >> 4) & 1;
        if (kt + 16 < 256) G2_LOAD(cur ^ 1, kt + 16);
        GEMM_KK(cur);
        __syncthreads();
    }
    float acc[8][8];
#pragma unroll
    for (int i = 0; i < 8; i++)
#pragma unroll
        for (int j2 = 0; j2 < 4; j2++)
            UNPACK2(acc[i][2 * j2], acc[i][2 * j2 + 1], acc2[i][j2]);

    float ls[8] = {}, lq[8] = {};
#pragma unroll
    for (int i = 0; i < 8; i++) {
        int m = row0 + ((i < 4) ? (ty * 4 + i) : (64 + ty * 4 + i - 4));
        if (m >= M) continue;
#pragma unroll
        for (int h = 0; h < 2; h++) {
            int c = h * 64 + tx * 4;
            float4 bb = *(const float4*)(bias + c);
            float4 o;
            o.x = acc[i][h * 4 + 0] + bb.x;
            o.y = acc[i][h * 4 + 1] + bb.y;
            o.z = acc[i][h * 4 + 2] + bb.z;
            o.w = acc[i][h * 4 + 3] + bb.w;
            *(float4*)(out + (size_t)m * 128 + c) = o;
            ls[h*4+0] += o.x; lq[h*4+0] = fmaf(o.x, o.x, lq[h*4+0]);
            ls[h*4+1] += o.y; lq[h*4+1] = fmaf(o.y, o.y, lq[h*4+1]);
            ls[h*4+2] += o.z; lq[h*4+2] = fmaf(o.z, o.z, lq[h*4+2]);
            ls[h*4+3] += o.w; lq[h*4+3] = fmaf(o.w, o.w, lq[h*4+3]);
        }
    }
#pragma unroll
    for (int h = 0; h < 2; h++)
#pragma unroll
        for (int j = 0; j < 4; j++) {
            int c = h * 64 + tx * 4 + j;
            atomicAdd(&sSum[c], ls[h*4+j]);
            atomicAdd(&sSq[c],  lq[h*4+j]);
        }
    __syncthreads();
    if (t < 128) {
        atomicAdd(&g_stat[512 + t], sSum[t]);
        atomicAdd(&g_stat[640 + t], sSq[t]);
    }
}

// ---------------- Threefry-2x32, key = (0, 42) -------------------------------------
__device__ __forceinline__ uint2 threefry2x32_042(uint32_t x0, uint32_t x1)
{
    const uint32_t k0 = 0u, k1 = 42u;
    const uint32_t k2 = k0 ^ k1 ^ 0x1BD11BDAu;
    x0 += k0; x1 += k1;
#define TF_R(r) { x0 += x1; x1 = __funnelshift_l(x1, x1, r); x1 ^= x0; }
    TF_R(13) TF_R(15) TF_R(26) TF_R(6)
    x0 += k1; x1 += k2 + 1u;
    TF_R(17) TF_R(29) TF_R(16) TF_R(24)
    x0 += k2; x1 += k0 + 2u;
    TF_R(13) TF_R(15) TF_R(26) TF_R(6)
    x0 += k0; x1 += k1 + 3u;
    TF_R(17) TF_R(29) TF_R(16) TF_R(24)
    x0 += k1; x1 += k2 + 4u;
    TF_R(13) TF_R(15) TF_R(26) TF_R(6)
    x0 += k2; x1 += k0 + 5u;
#undef TF_R
    return make_uint2(x0, x1);
}

// ---------------- outer BN (finalized in-block) + dropout ---------------------------
__global__ __launch_bounds__(256) void bn_dropout_kernel(
    const float* __restrict__ gam, const float* __restrict__ bet,
    float* __restrict__ out, int total, float invM)
{
    __shared__ __align__(16) float sScale2[128];
    __shared__ __align__(16) float sShift2[128];
    int t = threadIdx.x;
    if (t < 128) {
        float mu  = g_stat[512 + t] * invM;
        float msq = g_stat[640 + t] * invM;
        float var = msq - mu * mu;
        float sc = gam[t] * rsqrtf(var + 1e-5f);
        sScale2[t] = sc;
        sShift2[t] = bet[t] - mu * sc;
    }
    __syncthreads();

    int gid = blockIdx.x * blockDim.x + t;
    int i0 = gid * 4;
    if (i0 >= total) return;
    float4 v = *(float4*)(out + i0);
    int c = i0 & 127;
    float4 sc = *(const float4*)(sScale2 + c);
    float4 sh = *(const float4*)(sShift2 + c);
    float vals[4] = { fmaf(v.x, sc.x, sh.x), fmaf(v.y, sc.y, sh.y),
                      fmaf(v.z, sc.z, sh.z), fmaf(v.w, sc.w, sh.w) };
    float res[4];
#pragma unroll
    for (int j = 0; j < 4; j++) {
        uint2 o = threefry2x32_042(0u, (uint32_t)(i0 + j));
        uint32_t bits = o.x ^ o.y;
        float u = __uint_as_float((bits >> 9) | 0x3f800000u) - 1.0f;
        res[j] = (u < 0.8f) ? vals[j] * 1.25f : 0.0f;
    }
    *(float4*)(out + i0) = make_float4(res[0], res[1], res[2], res[3]);
}

// ---------------- launch -------------------------------------------------------------
extern "C" void kernel_launch(void* const* d_in, const int* in_sizes, int n_in,
                              void* d_out, int out_size)
{
    const float* x      = (const float*)d_in[0];
    const void*  ei     = d_in[1];
    const float* ea     = (const float*)d_in[2];
    const float* W_edge = (const float*)d_in[3];
    const float* b_edge = (const float*)d_in[4];
    const float* epsp   = (const float*)d_in[5];
    const float* W1     = (const float*)d_in[6];
    const float* b1     = (const float*)d_in[7];
    const float* g1     = (const float*)d_in[8];
    const float* beta1  = (const float*)d_in[9];
    const float* W2     = (const float*)d_in[10];
    const float* b2     = (const float*)d_in[11];
    const float* g_o    = (const float*)d_in[12];
    const float* beta_o = (const float*)d_in[13];
    float* out = (float*)d_out;

    int M = in_sizes[0] / EMB;     // 50000
    int E = in_sizes[1] / 2;       // 800000
    float invM = 1.0f / (float)M;
    int nScanBlocks = (M + 1023) / 1024;   // 49

    hist_kernel<<<(E + 255) / 256, 256>>>(ei, E, M);
    scan1_kernel<<<nScanBlocks, 256>>>(M);
    scan3_kernel<<<nScanBlocks, 256>>>(M, nScanBlocks);
    scatter_kernel<<<(E + 255) / 256, 256>>>(ei, E);
    aggr_kernel<<<AGGR_BLOCKS, 256>>>((const float4*)x, ea,
                                      (const float4*)W_edge, (const float4*)b_edge, M);
    int gM = (M + 127) / 128;
    gemm1_kernel<<<dim3(gM, 2), 256>>>(x, W1, b1, epsp, M);
    gemm2_kernel<<<gM, 256>>>(W2, b2, g1, beta1, out, M, invM);
    bn_dropout_kernel<<<(out_size / 4 + 255) / 256, 256>>>(g_o, beta_o, out, out_size, invM);
}